// round 3
// baseline (speedup 1.0000x reference)
#include <cuda_runtime.h>
#include <math.h>
#include <stdint.h>

// Problem constants
#define BB 64
#define CC 16
#define FF 2048
#define JT 25          // stored joints per row
#define NSER 24        // used joints (12 affected + 12 unaffected)
#define ROWSTRIDE 2049 // 2048 + 1 pad -> conflict-free banks
#define NTHREADS 768   // 24 warps, one per series
#define SMEM_U32 (NSER * ROWSTRIDE + NSER * 256)
#define SMEM_BYTES (SMEM_U32 * 4)

// Scratch (device globals: allocation-free)
__device__ float g_stat2[BB * CC * 16 * 12];   // (b,c,s,j)
__device__ float g_weff[5 * 16 * 16 * 12];     // (cls,c,s,j)

// ---------------------------------------------------------------------------
// warp helper: given a 256-bin histogram in smem, find the bin containing
// local rank r; returns bin and updates r to rank-within-bin. Warp-uniform.
// ---------------------------------------------------------------------------
__device__ __forceinline__ int warp_find_bin(const unsigned* hist, int lane, int& r) {
    unsigned c[8];
    unsigned run = 0;
#pragma unroll
    for (int t = 0; t < 8; t++) { c[t] = hist[lane * 8 + t]; run += c[t]; }
    // inclusive warp scan of per-lane totals
    unsigned inc = run;
#pragma unroll
    for (int d = 1; d < 32; d <<= 1) {
        unsigned v = __shfl_up_sync(0xffffffffu, inc, d);
        if (lane >= d) inc += v;
    }
    unsigned acc = inc - run;  // exclusive prefix for this lane's first bin
    int bin = -1, newr = 0;
#pragma unroll
    for (int t = 0; t < 8; t++) {
        if (bin < 0 && (int)acc <= r && r < (int)(acc + c[t])) {
            bin = lane * 8 + t;
            newr = r - (int)acc;
        }
        acc += c[t];
    }
    unsigned m = __ballot_sync(0xffffffffu, bin >= 0);
    int src = __ffs(m) - 1;
    bin  = __shfl_sync(0xffffffffu, bin, src);
    newr = __shfl_sync(0xffffffffu, newr, src);
    r = newr;
    return bin;
}

// ---------------------------------------------------------------------------
// Kernel A: per (b,c) block -> 24 series; moments + exact radix-select
// quantiles; writes stat2 rows [max,q25,med,q75,mean,std,range,kurt-3].
// ---------------------------------------------------------------------------
__global__ __launch_bounds__(NTHREADS, 1)
void stats_kernel(const float* __restrict__ features) {
    extern __shared__ unsigned sm[];
    float*    smf      = reinterpret_cast<float*>(sm);
    unsigned* hist_all = sm + NSER * ROWSTRIDE;

    const int bc  = blockIdx.x;          // b*16 + c
    const int tid = threadIdx.x;
    const float* src = features + (size_t)bc * (FF * JT);

    // Coalesced slab load, transposed to per-series rows in smem.
    for (int idx = tid; idx < FF * JT; idx += NTHREADS) {
        float v = __ldg(src + idx);
        int f = idx / 25;
        int j = idx - f * 25;
        if (j < NSER) smf[j * ROWSTRIDE + f] = v;
    }
    __syncthreads();

    const int w = tid >> 5;      // warp = series (0..23)
    const int lane = tid & 31;
    unsigned* krow = sm + w * ROWSTRIDE;
    unsigned* hist = hist_all + w * 256;

    // --- pass 1: moments + min/max + convert to monotone sortable keys ---
    float s1 = 0.f, s2 = 0.f, s3 = 0.f, s4 = 0.f;
    float mn = INFINITY, mx = -INFINITY;
#pragma unroll 4
    for (int i = 0; i < 64; i++) {
        int f = i * 32 + lane;
        unsigned raw = krow[f];
        float x = __uint_as_float(raw);
        s1 += x;
        float x2 = x * x;
        s2 += x2; s3 += x2 * x; s4 += x2 * x2;
        mn = fminf(mn, x); mx = fmaxf(mx, x);
        unsigned u = (raw & 0x80000000u) ? ~raw : (raw | 0x80000000u);
        krow[f] = u;
    }
#pragma unroll
    for (int d = 16; d; d >>= 1) {
        s1 += __shfl_xor_sync(0xffffffffu, s1, d);
        s2 += __shfl_xor_sync(0xffffffffu, s2, d);
        s3 += __shfl_xor_sync(0xffffffffu, s3, d);
        s4 += __shfl_xor_sync(0xffffffffu, s4, d);
        mn = fminf(mn, __shfl_xor_sync(0xffffffffu, mn, d));
        mx = fmaxf(mx, __shfl_xor_sync(0xffffffffu, mx, d));
    }
    __syncwarp();

    // --- level-1 histogram over top 8 key bits (shared by all 5 ranks) ---
#pragma unroll
    for (int t = 0; t < 8; t++) hist[lane * 8 + t] = 0u;
    __syncwarp();
#pragma unroll 4
    for (int i = 0; i < 64; i++)
        atomicAdd(&hist[krow[i * 32 + lane] >> 24], 1u);
    __syncwarp();

    const int ranks[5] = {511, 512, 1023, 1535, 1536};
    int b1[5], rl[5];
#pragma unroll
    for (int q = 0; q < 5; q++) {
        int r = ranks[q];
        b1[q] = warp_find_bin(hist, lane, r);
        rl[q] = r;
    }

    // --- per-rank refinement: 3 more 8-bit radix levels ---
    float qv[5];
#pragma unroll
    for (int q = 0; q < 5; q++) {
        unsigned prefix = (unsigned)b1[q] << 24;
        unsigned pmask  = 0xFF000000u;
        int r = rl[q];
        for (int shift = 16; shift >= 0; shift -= 8) {
            __syncwarp();
#pragma unroll
            for (int t = 0; t < 8; t++) hist[lane * 8 + t] = 0u;
            __syncwarp();
#pragma unroll 4
            for (int i = 0; i < 64; i++) {
                unsigned k = krow[i * 32 + lane];
                if ((k & pmask) == prefix)
                    atomicAdd(&hist[(k >> shift) & 0xFFu], 1u);
            }
            __syncwarp();
            int b = warp_find_bin(hist, lane, r);
            prefix |= (unsigned)b << shift;
            pmask  |= 0xFFu << shift;
        }
        unsigned u = prefix;
        u = (u & 0x80000000u) ? (u & 0x7FFFFFFFu) : ~u;  // key -> float
        qv[q] = __uint_as_float(u);
    }

    if (lane == 0) {
        const float n = 2048.f;
        float mean = s1 / n;
        float m2 = s2 / n, m3 = s3 / n, m4 = s4 / n;
        float varp = m2 - mean * mean;
        float var1 = varp * (n / (n - 1.f));     // ddof=1
        float sd = sqrtf(var1);
        float mu2 = mean * mean;
        float m4c = m4 - 4.f * mean * m3 + 6.f * mu2 * m2 - 3.f * mu2 * mu2;
        float kurt = m4c / (var1 * var1) - 3.f;
        // q25: pos=511.75 -> 0.25*xs[511]+0.75*xs[512]; q75: pos=1535.25
        float q25 = 0.25f * qv[0] + 0.75f * qv[1];
        float med = qv[2];
        float q75 = 0.75f * qv[3] + 0.25f * qv[4];

        int base = (w < 12) ? 0 : 8;          // affected rows 0-7, unaffected 8-15
        int col  = (w < 12) ? w : (w - 12);
        float* o = g_stat2 + ((size_t)bc * 16 + base) * 12 + col;
        o[0 * 12] = mx;
        o[1 * 12] = q25;
        o[2 * 12] = med;
        o[3 * 12] = q75;
        o[4 * 12] = mean;
        o[5 * 12] = sd;
        o[6 * 12] = mx - mn;
        o[7 * 12] = kurt;
    }
}

// ---------------------------------------------------------------------------
// Kernel B: Weff[cls,c,s,j] = sum_e Wl[cls, e*16+s] * W2[e,c,j]
// ---------------------------------------------------------------------------
__global__ void weff_kernel(const float* __restrict__ W2, const float* __restrict__ Wl) {
    int idx = blockIdx.x * blockDim.x + threadIdx.x;
    if (idx >= 5 * 16 * 16 * 12) return;
    int j   = idx % 12;
    int s   = (idx / 12) % 16;
    int c   = (idx / 192) % 16;
    int cls = idx / 3072;
    float acc = 0.f;
#pragma unroll 8
    for (int e = 0; e < 64; e++)
        acc += Wl[cls * 1024 + e * 16 + s] * W2[(e * 16 + c) * 12 + j];
    g_weff[idx] = acc;
}

// ---------------------------------------------------------------------------
// Kernel C: logits[b,cls] = sum stat2[b,:]*Weff[cls,:] + sum b2*Wl + bl
// one warp per output (320 warps).
// ---------------------------------------------------------------------------
__global__ void logits_kernel(const float* __restrict__ Wl,
                              const float* __restrict__ b2,
                              const float* __restrict__ bl,
                              float* __restrict__ out) {
    int wid = blockIdx.x;            // 0..319
    int b = wid / 5, cls = wid % 5;
    int lane = threadIdx.x;
    const float* st = g_stat2 + (size_t)b * 3072;
    const float* wf = g_weff + (size_t)cls * 3072;
    float acc = 0.f;
    for (int i = lane; i < 3072; i += 32) acc += st[i] * wf[i];
    for (int k = lane; k < 1024; k += 32) acc += b2[k >> 4] * Wl[cls * 1024 + k];
#pragma unroll
    for (int d = 16; d; d >>= 1) acc += __shfl_xor_sync(0xffffffffu, acc, d);
    if (lane == 0) out[b * 5 + cls] = acc + bl[cls];
}

// ---------------------------------------------------------------------------
extern "C" void kernel_launch(void* const* d_in, const int* in_sizes, int n_in,
                              void* d_out, int out_size) {
    const float* features = (const float*)d_in[0];
    // d_in[1] = W1, d_in[2] = b1 : dead in the reference (result discarded)
    const float* W2 = (const float*)d_in[3];
    const float* b2 = (const float*)d_in[4];
    const float* Wl = (const float*)d_in[5];
    const float* bl = (const float*)d_in[6];
    float* out = (float*)d_out;

    cudaFuncSetAttribute(stats_kernel,
                         cudaFuncAttributeMaxDynamicSharedMemorySize, SMEM_BYTES);

    stats_kernel<<<BB * CC, NTHREADS, SMEM_BYTES>>>(features);
    weff_kernel<<<(5 * 16 * 16 * 12 + 255) / 256, 256>>>(W2, Wl);
    logits_kernel<<<BB * 5, 32>>>(Wl, b2, bl, out);
}

// round 5
// speedup vs baseline: 1.1042x; 1.1042x over previous
#include <cuda_runtime.h>
#include <math.h>
#include <stdint.h>

// Problem constants
#define BB 64
#define CC 16
#define FF 2048
#define JT 25            // stored joints per feature row
#define SPB 12           // series per block (half of the 24 used joints)
#define NT 384           // 12 warps, one per series
#define RS 2049          // padded row stride (words)
#define DATA_WORDS (SPB * RS)       // 24588 words = 98352 B (dominant region)
#define HISTW 2048                  // per-warp level-1 histogram bins
#define SMEM_BYTES (DATA_WORDS * 4)

__device__ float g_stat2[BB * CC * 16 * 12];   // (b, c, s, j)

// ---------------------------------------------------------------------------
// 256-bin histogram rank search (warp-uniform r). Returns bin; updates r to
// rank-within-bin; outputs the bin's count.
// ---------------------------------------------------------------------------
__device__ __forceinline__ int warp_find_bin256(const unsigned* hist, int lane,
                                                int& r, int& bincount) {
    const unsigned full = 0xffffffffu;
    unsigned c[8]; unsigned run = 0;
#pragma unroll
    for (int t = 0; t < 8; t++) { c[t] = hist[lane * 8 + t]; run += c[t]; }
    unsigned inc = run;
#pragma unroll
    for (int d = 1; d < 32; d <<= 1) {
        unsigned v = __shfl_up_sync(full, inc, d);
        if (lane >= d) inc += v;
    }
    unsigned acc = inc - run;
    int bin = -1, newr = 0; unsigned bc = 0;
#pragma unroll
    for (int t = 0; t < 8; t++) {
        if (bin < 0 && (int)acc <= r && r < (int)(acc + c[t])) {
            bin = lane * 8 + t;
            newr = r - (int)acc;
            bc = c[t];
        }
        acc += c[t];
    }
    unsigned m = __ballot_sync(full, bin >= 0);
    int srcl = __ffs(m) - 1;
    bin      = __shfl_sync(full, bin, srcl);
    newr     = __shfl_sync(full, newr, srcl);
    bc       = __shfl_sync(full, bc, srcl);
    r = newr;
    bincount = (int)bc;
    return bin;
}

// ---------------------------------------------------------------------------
// Kernel A: one block per (b,c,half); 12 warps, one series each.
// Keys register-resident; 11-bit level-1 histogram; refinement by register
// rescans; final <=32 survivors bitonic-sorted in registers.
// ---------------------------------------------------------------------------
__global__ __launch_bounds__(NT, 1)
void stats_kernel(const float* __restrict__ features) {
    extern __shared__ unsigned sm[];
    const unsigned full = 0xffffffffu;

    const int blk  = blockIdx.x;
    const int bc   = blk >> 1;
    const int half = blk & 1;
    const int tid  = threadIdx.x;

    const float* src = features + (size_t)bc * (FF * JT) + half * 12;
    float* smf = reinterpret_cast<float*>(sm);

    // ---- phase 1: load the 12 needed joints, transpose to rows ----
    // NT = 32*12, so each thread keeps a fixed jj and strides f by 32.
    {
        int f  = tid / 12;
        int jj = tid - f * 12;
#pragma unroll 8
        for (int k = 0; k < 64; k++, f += 32)
            smf[jj * RS + f] = __ldg(src + f * JT + jj);
    }
    __syncthreads();

    const int w    = tid >> 5;
    const int lane = tid & 31;

    // ---- phase 2: series -> registers; moments; monotone sortable keys ----
    unsigned key[64];
    float s1 = 0.f, s2 = 0.f, s3 = 0.f, s4 = 0.f;
    float mn = INFINITY, mx = -INFINITY;
    const unsigned* row = sm + w * RS;
#pragma unroll
    for (int i = 0; i < 64; i++) {
        unsigned raw = row[i * 32 + lane];
        float x = __uint_as_float(raw);
        s1 += x;
        float x2 = x * x;
        s2 += x2; s3 += x2 * x; s4 += x2 * x2;
        mn = fminf(mn, x); mx = fmaxf(mx, x);
        key[i] = (raw & 0x80000000u) ? ~raw : (raw | 0x80000000u);
    }
#pragma unroll
    for (int d = 16; d; d >>= 1) {
        s1 += __shfl_xor_sync(full, s1, d);
        s2 += __shfl_xor_sync(full, s2, d);
        s3 += __shfl_xor_sync(full, s3, d);
        s4 += __shfl_xor_sync(full, s4, d);
        mn = fminf(mn, __shfl_xor_sync(full, mn, d));
        mx = fmaxf(mx, __shfl_xor_sync(full, mx, d));
    }
    __syncthreads();   // series now in registers; smem reusable per-warp

    // ---- phase 3: per-warp 2048-bin level-1 histogram (top 11 key bits) ----
    unsigned* wh = sm + w * HISTW;
#pragma unroll
    for (int t = 0; t < 64; t++) wh[t * 32 + lane] = 0u;
    __syncwarp();
#pragma unroll
    for (int i = 0; i < 64; i++) atomicAdd(&wh[key[i] >> 21], 1u);
    __syncwarp();

    // chunk sums: 64 chunks of 32 bins (XOR-rotated reads, conflict-free)
    unsigned cs0 = 0, cs1 = 0;
#pragma unroll
    for (int k = 0; k < 32; k++) {
        int kk = (k + lane) & 31;
        cs0 += wh[lane * 32 + kk];
        cs1 += wh[(lane + 32) * 32 + kk];
    }
    unsigned inc0 = cs0, inc1 = cs1;
#pragma unroll
    for (int d = 1; d < 32; d <<= 1) {
        unsigned v = __shfl_up_sync(full, inc0, d); if (lane >= d) inc0 += v;
        v = __shfl_up_sync(full, inc1, d);          if (lane >= d) inc1 += v;
    }
    unsigned tot0 = __shfl_sync(full, inc0, 31);
    inc1 += tot0;
    unsigned exc0 = inc0 - cs0, exc1 = inc1 - cs1;

    // ---- phase 4: level-1 bin, local rank, bin count for all 5 ranks ----
    const int ranks[5] = {511, 512, 1023, 1535, 1536};
    int binq[5], lrq[5], cnq[5];
#pragma unroll
    for (int q = 0; q < 5; q++) {
        int r = ranks[q];
        bool in0 = ((int)exc0 <= r) && (r < (int)inc0);
        unsigned m0 = __ballot_sync(full, in0);
        int chunk, lr;
        if (m0) {
            int l = __ffs(m0) - 1;
            chunk = l;
            lr = r - (int)__shfl_sync(full, exc0, l);
        } else {
            bool in1 = ((int)exc1 <= r) && (r < (int)inc1);
            unsigned m1 = __ballot_sync(full, in1);
            int l = __ffs(m1) - 1;
            chunk = 32 + l;
            lr = r - (int)__shfl_sync(full, exc1, l);
        }
        unsigned c = wh[chunk * 32 + lane];
        unsigned ic = c;
#pragma unroll
        for (int d = 1; d < 32; d <<= 1) {
            unsigned v = __shfl_up_sync(full, ic, d); if (lane >= d) ic += v;
        }
        unsigned ex = ic - c;
        bool hit = ((int)ex <= lr) && (lr < (int)ic);
        unsigned hm = __ballot_sync(full, hit);
        int hl = __ffs(hm) - 1;
        binq[q] = chunk * 32 + hl;
        lrq[q]  = lr - (int)__shfl_sync(full, ex, hl);
        cnq[q]  = (int)__shfl_sync(full, c, hl);
    }
    __syncwarp();

    // ---- phase 5: per-rank selection. Refinement rescans REGISTER keys. ----
    unsigned* h2  = wh;        // 256-word refinement hist (level-1 now dead)
    unsigned* b32 = wh + 256;  // 32-word final staging
    float qv[5];
    unsigned havemask = 0;
    const int shifts[3] = {13, 5, 0};

#pragma unroll 1
    for (int q = 0; q < 5; q++) {
        if (havemask & (1u << q)) continue;
        unsigned prefix = (unsigned)binq[q] << 21;
        unsigned pmask  = 0xFFE00000u;
        int lr  = lrq[q];
        int cnt = cnq[q];

#pragma unroll 1
        for (int st = 0; st < 3 && cnt > 32; st++) {
            int sh = shifts[st];
            for (int t = lane; t < 256; t += 32) h2[t] = 0u;
            __syncwarp();
#pragma unroll
            for (int i = 0; i < 64; i++) {
                unsigned k = key[i];
                if ((k & pmask) == prefix)
                    atomicAdd(&h2[(k >> sh) & 0xFFu], 1u);
            }
            __syncwarp();
            int bcnt;
            int b = warp_find_bin256(h2, lane, lr, bcnt);
            prefix |= (unsigned)b << sh;
            pmask  |= 0xFFu << sh;
            cnt = bcnt;
            __syncwarp();
        }

        unsigned k0, k1;
        bool has1 = (lr + 1 < cnt);
        if (cnt <= 32) {
            // gather survivors into 32-word staging, then register bitonic
            int pos = 0;
#pragma unroll
            for (int i = 0; i < 64; i++) {
                bool p = (key[i] & pmask) == prefix;
                unsigned m = __ballot_sync(full, p);
                if (p) b32[pos + __popc(m & ((1u << lane) - 1u))] = key[i];
                pos += __popc(m);
            }
            __syncwarp();
            unsigned v = (lane < cnt) ? b32[lane] : 0xFFFFFFFFu;
#pragma unroll
            for (int k2 = 2; k2 <= 32; k2 <<= 1) {
#pragma unroll
                for (int j = k2 >> 1; j > 0; j >>= 1) {
                    unsigned o = __shfl_xor_sync(full, v, j);
                    bool keepMin = ((lane & j) == 0) == ((lane & k2) == 0);
                    unsigned lo = min(v, o), hi = max(v, o);
                    v = keepMin ? lo : hi;
                }
            }
            k0 = __shfl_sync(full, v, lr);
            k1 = __shfl_sync(full, v, (lr + 1) & 31);
            __syncwarp();
        } else {
            // all survivors bit-identical (every bit determined)
            k0 = prefix;
            k1 = prefix;
        }

        unsigned u0 = (k0 & 0x80000000u) ? (k0 & 0x7fffffffu) : ~k0;
        qv[q] = __uint_as_float(u0);
        if ((q == 0 || q == 3) && has1) {
            // rank+1 is the next element of the SAME final subset: valid reuse
            unsigned u1 = (k1 & 0x80000000u) ? (k1 & 0x7fffffffu) : ~k1;
            qv[q + 1] = __uint_as_float(u1);
            havemask |= 1u << (q + 1);
        }
    }

    // ---- phase 6: finalize + write stat2 ----
    if (lane == 0) {
        const float n = 2048.f;
        float mean = s1 / n;
        float m2 = s2 / n, m3 = s3 / n, m4 = s4 / n;
        float varp = m2 - mean * mean;
        float var1 = varp * (n / (n - 1.f));
        float sd = sqrtf(var1);
        float mu2 = mean * mean;
        float m4c = m4 - 4.f * mean * m3 + 6.f * mu2 * m2 - 3.f * mu2 * mu2;
        float kurt = m4c / (var1 * var1) - 3.f;
        float q25 = 0.25f * qv[0] + 0.75f * qv[1];   // pos 511.75
        float med = qv[2];                            // pos 1023
        float q75 = 0.75f * qv[3] + 0.25f * qv[4];   // pos 1535.25

        int base = half ? 8 : 0;   // affected -> rows 0-7, unaffected -> 8-15
        float* o = g_stat2 + ((size_t)bc * 16 + base) * 12 + w;
        o[0 * 12] = mx;
        o[1 * 12] = q25;
        o[2 * 12] = med;
        o[3 * 12] = q75;
        o[4 * 12] = mean;
        o[5 * 12] = sd;
        o[6 * 12] = mx - mn;
        o[7 * 12] = kurt;
    }
}

// ---------------------------------------------------------------------------
// Kernel B (fused epilogue): one block per class.
//   weff[c,s,j] = sum_e Wl[cls,e*16+s] * W2[e,c,j]   (into smem)
//   logits[b,cls] = dot(stat2[b], weff) + sum_k b2[k/16]*Wl[cls,k] + bl[cls]
// ---------------------------------------------------------------------------
__global__ __launch_bounds__(256)
void epilogue_kernel(const float* __restrict__ W2, const float* __restrict__ b2,
                     const float* __restrict__ Wl, const float* __restrict__ bl,
                     float* __restrict__ out) {
    __shared__ float wf[3072];
    __shared__ float wl_s[1024];
    __shared__ float sbias;
    const unsigned full = 0xffffffffu;
    int cls = blockIdx.x;
    int tid = threadIdx.x;

    for (int i = tid; i < 1024; i += 256) wl_s[i] = Wl[cls * 1024 + i];
    __syncthreads();

    for (int idx = tid; idx < 3072; idx += 256) {
        int j = idx % 12;
        int s = (idx / 12) & 15;
        int c = idx / 192;
        float a = 0.f;
#pragma unroll 8
        for (int e = 0; e < 64; e++)
            a += wl_s[e * 16 + s] * __ldg(&W2[(e * 16 + c) * 12 + j]);
        wf[idx] = a;
    }
    if (tid < 32) {
        float a = 0.f;
        for (int k = tid; k < 1024; k += 32)
            a += b2[k >> 4] * wl_s[k];
#pragma unroll
        for (int d = 16; d; d >>= 1) a += __shfl_xor_sync(full, a, d);
        if (tid == 0) sbias = a + bl[cls];
    }
    __syncthreads();

    int w = tid >> 5, lane = tid & 31;
    for (int b = w; b < 64; b += 8) {
        const float* st = g_stat2 + (size_t)b * 3072;
        float a = 0.f;
        for (int i = lane; i < 3072; i += 32) a += st[i] * wf[i];
#pragma unroll
        for (int d = 16; d; d >>= 1) a += __shfl_xor_sync(full, a, d);
        if (lane == 0) out[b * 5 + cls] = a + sbias;
    }
}

// ---------------------------------------------------------------------------
extern "C" void kernel_launch(void* const* d_in, const int* in_sizes, int n_in,
                              void* d_out, int out_size) {
    const float* features = (const float*)d_in[0];
    // d_in[1]=W1, d_in[2]=b1 : dead in the reference (result discarded)
    const float* W2 = (const float*)d_in[3];
    const float* b2 = (const float*)d_in[4];
    const float* Wl = (const float*)d_in[5];
    const float* bl = (const float*)d_in[6];
    float* out = (float*)d_out;

    cudaFuncSetAttribute(stats_kernel,
                         cudaFuncAttributeMaxDynamicSharedMemorySize,
                         SMEM_BYTES);

    stats_kernel<<<BB * CC * 2, NT, SMEM_BYTES>>>(features);
    epilogue_kernel<<<5, 256>>>(W2, b2, Wl, bl, out);
}